// round 3
// baseline (speedup 1.0000x reference)
#include <cuda_runtime.h>
#include <cuda_bf16.h>

#define NB   32
#define AA   512
#define HH   512
#define WW   512
#define CC   3
#define OUTN 512
#define ITERS 5

// scratch for the coordinate maps (allocation-free rule)
__device__ float g_gx[NB * OUTN];  // width coords  (from atty)
__device__ float g_gy[NB * OUTN];  // height coords (from attx)

// Offsets of the per-level arrays for the associative-scan recursion
// (lengths 512,256,128,64,32,16,8,4,2 -> total 1022)
__device__ __constant__ int c_off[9] = {0, 512, 768, 896, 960, 992, 1008, 1016, 1020};

// ---------------------------------------------------------------------------
// Kernel 1: water-fill + jax-exact associative-scan cumsum + inverse-CDF
// coords. One CTA per sample, 512 threads.
// ---------------------------------------------------------------------------
__global__ void __launch_bounds__(512) waterfill_coords_kernel(
    const float* __restrict__ attx, const float* __restrict__ atty)
{
    const int n   = blockIdx.x;
    const int tid = threadIdx.x;   // 0..511

    __shared__ float sh_red[16];
    __shared__ float s_a [1022];   // per-level input arrays (a_L)
    __shared__ float s_cs[1022];   // per-level scan results

    float ax = attx[n * AA + tid] * (float)OUTN;
    float ay = atty[n * AA + tid] * (float)OUTN;

    auto block_reduce = [&](float v, bool isMax) -> float {
        #pragma unroll
        for (int o = 16; o > 0; o >>= 1) {
            float other = __shfl_xor_sync(0xffffffffu, v, o);
            v = isMax ? fmaxf(v, other) : (v + other);
        }
        if ((tid & 31) == 0) sh_red[tid >> 5] = v;
        __syncthreads();
        if (tid == 0) {
            float r = sh_red[0];
            #pragma unroll
            for (int i = 1; i < 16; i++)
                r = isMax ? fmaxf(r, sh_red[i]) : (r + sh_red[i]);
            sh_red[0] = r;
        }
        __syncthreads();
        float r = sh_red[0];
        __syncthreads();
        return r;
    };

    const float thr0 = 4.0f;  // SCALE*DENSE*H/A = 1*4*512/512

    #pragma unroll 1
    for (int j = 0; j < ITERS; j++) {
        float mx = block_reduce(ax, true);
        float my = block_reduce(ay, true);
        float thr = fminf(mx, my);
        if (j == 0) thr = fminf(thr, thr0);
        ax = fminf(ax, thr);
        ay = fminf(ay, thr);
        float sx = block_reduce(ax, false);
        float sy = block_reduce(ay, false);
        ax = ax + ((float)OUTN - sx) / (float)AA;
        ay = ay + ((float)OUTN - sy) / (float)AA;
    }

    if (tid == 0) { ax = 1.0f; ay = 1.0f; }

    // jax lax.associative_scan cumsum (exact recursion replication) + coords.
    // axis==0 -> process ax (produces gy), axis==1 -> ay (produces gx).
    #pragma unroll 1
    for (int axis = 0; axis < 2; axis++) {
        const float aval = (axis == 0) ? ax : ay;
        s_a[tid] = aval;
        __syncthreads();

        // down-sweep: reduced[i] = a[2i] + a[2i+1]
        #pragma unroll
        for (int L = 0; L < 8; L++) {
            const int half = 256 >> L;           // length of level L+1
            if (tid < half) {
                s_a[c_off[L + 1] + tid] =
                    s_a[c_off[L] + 2 * tid] + s_a[c_off[L] + 2 * tid + 1];
            }
            __syncthreads();
        }
        // base case: level 8 has length 2
        if (tid == 0) {
            s_cs[c_off[8] + 0] = s_a[c_off[8] + 0];
            s_cs[c_off[8] + 1] = s_a[c_off[8] + 0] + s_a[c_off[8] + 1];
        }
        __syncthreads();
        // up-sweep: cs_L[2i+1] = odd[i]; cs_L[0] = a_L[0];
        //           cs_L[2i]   = odd[i-1] + a_L[2i]  (i>=1)
        #pragma unroll
        for (int L = 7; L >= 0; L--) {
            const int half = 256 >> L;           // length of level L+1
            if (tid < half) {
                const float odd_i = s_cs[c_off[L + 1] + tid];
                s_cs[c_off[L] + 2 * tid + 1] = odd_i;
                s_cs[c_off[L] + 2 * tid] =
                    (tid == 0) ? s_a[c_off[L]]
                               : (s_cs[c_off[L + 1] + tid - 1] + s_a[c_off[L] + 2 * tid]);
            }
            __syncthreads();
        }
        // now s_cs[0..511] = cumsum, s_a[0..511] = att values

        const float tot  = s_cs[AA - 1];
        const float step = tot / (float)OUTN;
        const float t    = (float)(tid + 1) * step;

        // searchsorted(cs, t, side='left') — standard bisection, identical
        // comparison sequence to jnp's method='scan'
        int lo = 0, hi = AA;
        while (lo < hi) {
            int mid = (lo + hi) >> 1;
            if (s_cs[mid] < t) lo = mid + 1; else hi = mid;
        }
        int j = min(lo, AA - 1);
        float prev = (j > 0) ? s_cs[j - 1] : 0.0f;
        float frac = (t - prev) / fmaxf(s_a[j], 1e-12f);
        float coord = ((float)j + frac) / (float)AA * 2.0f - 1.0f;

        if (axis == 0) g_gy[n * OUTN + tid] = coord;
        else           g_gx[n * OUTN + tid] = coord;
        __syncthreads();
    }
}

// ---------------------------------------------------------------------------
// Kernel 2: bilinear grid sample + grid output.
// blockIdx.x = output row ho, blockIdx.y = sample n, threadIdx.x = wo.
// ---------------------------------------------------------------------------
__global__ void __launch_bounds__(512) grid_sample_kernel(
    const float* __restrict__ data, float* __restrict__ out, int writeGrid)
{
    const int wo = threadIdx.x;
    const int ho = blockIdx.x;
    const int n  = blockIdx.y;

    const float xg = g_gx[n * OUTN + wo];
    const float yg = g_gy[n * OUTN + ho];

    const float x = (xg + 1.0f) * ((float)WW * 0.5f) - 0.5f;
    const float y = (yg + 1.0f) * ((float)HH * 0.5f) - 0.5f;

    const float x0f = floorf(x);
    const float y0f = floorf(y);
    const int x0 = (int)x0f;
    const int y0 = (int)y0f;
    const int x1 = x0 + 1;
    const int y1 = y0 + 1;

    const float wx1 = x - x0f, wx0 = 1.0f - wx1;
    const float wy1 = y - y0f, wy0 = 1.0f - wy1;

    const bool vx0 = (x0f >= 0.0f) & (x0f < (float)WW);
    const bool vx1 = (x0f + 1.0f >= 0.0f) & (x0f + 1.0f < (float)WW);
    const bool vy0 = (y0f >= 0.0f) & (y0f < (float)HH);
    const bool vy1 = (y0f + 1.0f >= 0.0f) & (y0f + 1.0f < (float)HH);

    const int x0c = min(max(x0, 0), WW - 1);
    const int x1c = min(max(x1, 0), WW - 1);
    const int y0c = min(max(y0, 0), HH - 1);
    const int y1c = min(max(y1, 0), HH - 1);

    const float w00 = wx0 * wy0, w01 = wx1 * wy0;
    const float w10 = wx0 * wy1, w11 = wx1 * wy1;

    #pragma unroll
    for (int c = 0; c < CC; c++) {
        const float* __restrict__ plane = data + ((size_t)(n * CC + c)) * HH * WW;
        const float* __restrict__ r0 = plane + (size_t)y0c * WW;
        const float* __restrict__ r1 = plane + (size_t)y1c * WW;
        float v00 = (vx0 & vy0) ? __ldg(r0 + x0c) : 0.0f;
        float v01 = (vx1 & vy0) ? __ldg(r0 + x1c) : 0.0f;
        float v10 = (vx0 & vy1) ? __ldg(r1 + x0c) : 0.0f;
        float v11 = (vx1 & vy1) ? __ldg(r1 + x1c) : 0.0f;
        float val = v00 * w00 + v01 * w01 + v10 * w10 + v11 * w11;
        out[(((size_t)(n * CC + c)) * OUTN + ho) * OUTN + wo] = val;
    }

    if (writeGrid) {
        float2* g = (float2*)(out + (size_t)NB * CC * OUTN * OUTN);
        g[((size_t)n * OUTN + ho) * OUTN + wo] = make_float2(xg, yg);
    }
}

extern "C" void kernel_launch(void* const* d_in, const int* in_sizes, int n_in,
                              void* d_out, int out_size)
{
    const float* data = (const float*)d_in[0];
    const float* attx = (const float*)d_in[1];
    const float* atty = (const float*)d_in[2];
    float* out = (float*)d_out;

    const long long sampled_elems = (long long)NB * CC * OUTN * OUTN;            // 25,165,824
    const long long grid_elems    = (long long)NB * OUTN * OUTN * 2;             // 16,777,216
    const int writeGrid = ((long long)out_size >= sampled_elems + grid_elems) ? 1 : 0;

    waterfill_coords_kernel<<<NB, 512>>>(attx, atty);
    dim3 grid2(OUTN, NB);
    grid_sample_kernel<<<grid2, 512>>>(data, out, writeGrid);
}

// round 4
// speedup vs baseline: 1.0208x; 1.0208x over previous
#include <cuda_runtime.h>
#include <cuda_bf16.h>

#define NB   32
#define AA   512
#define HH   512
#define WW   512
#define CC   3
#define OUTN 512
#define ITERS 5

// scratch for the coordinate maps (allocation-free rule)
__device__ float g_gx[NB * OUTN];  // width coords  (from atty)
__device__ float g_gy[NB * OUTN];  // height coords (from attx)

// Offsets of the per-level arrays for the associative-scan recursion
// (lengths 512,256,128,64,32,16,8,4,2 -> total 1022)
__device__ __constant__ int c_off[9] = {0, 512, 768, 896, 960, 992, 1008, 1016, 1020};

// ---------------------------------------------------------------------------
// Kernel 1: water-fill + jax-exact associative-scan cumsum + inverse-CDF
// coords. One CTA per sample, 512 threads.
// ---------------------------------------------------------------------------
__global__ void __launch_bounds__(512) waterfill_coords_kernel(
    const float* __restrict__ attx, const float* __restrict__ atty)
{
    const int n   = blockIdx.x;
    const int tid = threadIdx.x;   // 0..511

    __shared__ float sh_red[16];
    __shared__ float s_a [1022];   // per-level input arrays (a_L)
    __shared__ float s_cs[1022];   // per-level scan results

    float ax = attx[n * AA + tid] * (float)OUTN;
    float ay = atty[n * AA + tid] * (float)OUTN;

    auto block_reduce = [&](float v, bool isMax) -> float {
        #pragma unroll
        for (int o = 16; o > 0; o >>= 1) {
            float other = __shfl_xor_sync(0xffffffffu, v, o);
            v = isMax ? fmaxf(v, other) : (v + other);
        }
        if ((tid & 31) == 0) sh_red[tid >> 5] = v;
        __syncthreads();
        if (tid == 0) {
            float r = sh_red[0];
            #pragma unroll
            for (int i = 1; i < 16; i++)
                r = isMax ? fmaxf(r, sh_red[i]) : (r + sh_red[i]);
            sh_red[0] = r;
        }
        __syncthreads();
        float r = sh_red[0];
        __syncthreads();
        return r;
    };

    const float thr0 = 4.0f;  // SCALE*DENSE*H/A = 1*4*512/512

    #pragma unroll 1
    for (int j = 0; j < ITERS; j++) {
        float mx = block_reduce(ax, true);
        float my = block_reduce(ay, true);
        float thr = fminf(mx, my);
        if (j == 0) thr = fminf(thr, thr0);
        ax = fminf(ax, thr);
        ay = fminf(ay, thr);
        float sx = block_reduce(ax, false);
        float sy = block_reduce(ay, false);
        ax = ax + ((float)OUTN - sx) / (float)AA;
        ay = ay + ((float)OUTN - sy) / (float)AA;
    }

    if (tid == 0) { ax = 1.0f; ay = 1.0f; }

    // jax lax.associative_scan cumsum (exact recursion replication) + coords.
    // axis==0 -> process ax (produces gy), axis==1 -> ay (produces gx).
    #pragma unroll 1
    for (int axis = 0; axis < 2; axis++) {
        const float aval = (axis == 0) ? ax : ay;
        s_a[tid] = aval;
        __syncthreads();

        // down-sweep: reduced[i] = a[2i] + a[2i+1]
        #pragma unroll
        for (int L = 0; L < 8; L++) {
            const int half = 256 >> L;           // length of level L+1
            if (tid < half) {
                s_a[c_off[L + 1] + tid] =
                    s_a[c_off[L] + 2 * tid] + s_a[c_off[L] + 2 * tid + 1];
            }
            __syncthreads();
        }
        // base case: level 8 has length 2
        if (tid == 0) {
            s_cs[c_off[8] + 0] = s_a[c_off[8] + 0];
            s_cs[c_off[8] + 1] = s_a[c_off[8] + 0] + s_a[c_off[8] + 1];
        }
        __syncthreads();
        // up-sweep: cs_L[2i+1] = odd[i]; cs_L[0] = a_L[0];
        //           cs_L[2i]   = odd[i-1] + a_L[2i]  (i>=1)
        #pragma unroll
        for (int L = 7; L >= 0; L--) {
            const int half = 256 >> L;           // length of level L+1
            if (tid < half) {
                const float odd_i = s_cs[c_off[L + 1] + tid];
                s_cs[c_off[L] + 2 * tid + 1] = odd_i;
                s_cs[c_off[L] + 2 * tid] =
                    (tid == 0) ? s_a[c_off[L]]
                               : (s_cs[c_off[L + 1] + tid - 1] + s_a[c_off[L] + 2 * tid]);
            }
            __syncthreads();
        }
        // now s_cs[0..511] = cumsum, s_a[0..511] = att values

        const float tot  = s_cs[AA - 1];
        const float step = tot / (float)OUTN;
        const float t    = (float)(tid + 1) * step;

        // searchsorted(cs, t, side='left') — standard bisection, identical
        // comparison sequence to jnp's method='scan'
        int lo = 0, hi = AA;
        while (lo < hi) {
            int mid = (lo + hi) >> 1;
            if (s_cs[mid] < t) lo = mid + 1; else hi = mid;
        }
        int j = min(lo, AA - 1);
        float prev = (j > 0) ? s_cs[j - 1] : 0.0f;
        float frac = (t - prev) / fmaxf(s_a[j], 1e-12f);
        float coord = ((float)j + frac) / (float)AA * 2.0f - 1.0f;

        if (axis == 0) g_gy[n * OUTN + tid] = coord;
        else           g_gx[n * OUTN + tid] = coord;
        __syncthreads();
    }
}

// ---------------------------------------------------------------------------
// Kernel 2: bilinear grid sample + grid output.
// blockIdx.x = output row ho, blockIdx.y = sample n, threadIdx.x = wo.
// ---------------------------------------------------------------------------
__global__ void __launch_bounds__(512) grid_sample_kernel(
    const float* __restrict__ data, float* __restrict__ out, int writeGrid)
{
    const int wo = threadIdx.x;
    const int ho = blockIdx.x;
    const int n  = blockIdx.y;

    const float xg = g_gx[n * OUTN + wo];
    const float yg = g_gy[n * OUTN + ho];

    const float x = (xg + 1.0f) * ((float)WW * 0.5f) - 0.5f;
    const float y = (yg + 1.0f) * ((float)HH * 0.5f) - 0.5f;

    const float x0f = floorf(x);
    const float y0f = floorf(y);
    const int x0 = (int)x0f;
    const int y0 = (int)y0f;
    const int x1 = x0 + 1;
    const int y1 = y0 + 1;

    const float wx1 = x - x0f, wx0 = 1.0f - wx1;
    const float wy1 = y - y0f, wy0 = 1.0f - wy1;

    const bool vx0 = (x0f >= 0.0f) & (x0f < (float)WW);
    const bool vx1 = (x0f + 1.0f >= 0.0f) & (x0f + 1.0f < (float)WW);
    const bool vy0 = (y0f >= 0.0f) & (y0f < (float)HH);
    const bool vy1 = (y0f + 1.0f >= 0.0f) & (y0f + 1.0f < (float)HH);

    const int x0c = min(max(x0, 0), WW - 1);
    const int x1c = min(max(x1, 0), WW - 1);
    const int y0c = min(max(y0, 0), HH - 1);
    const int y1c = min(max(y1, 0), HH - 1);

    const float w00 = wx0 * wy0, w01 = wx1 * wy0;
    const float w10 = wx0 * wy1, w11 = wx1 * wy1;

    #pragma unroll
    for (int c = 0; c < CC; c++) {
        const float* __restrict__ plane = data + ((size_t)(n * CC + c)) * HH * WW;
        const float* __restrict__ r0 = plane + (size_t)y0c * WW;
        const float* __restrict__ r1 = plane + (size_t)y1c * WW;
        float v00 = (vx0 & vy0) ? __ldg(r0 + x0c) : 0.0f;
        float v01 = (vx1 & vy0) ? __ldg(r0 + x1c) : 0.0f;
        float v10 = (vx0 & vy1) ? __ldg(r1 + x0c) : 0.0f;
        float v11 = (vx1 & vy1) ? __ldg(r1 + x1c) : 0.0f;
        float val = v00 * w00 + v01 * w01 + v10 * w10 + v11 * w11;
        out[(((size_t)(n * CC + c)) * OUTN + ho) * OUTN + wo] = val;
    }

    if (writeGrid) {
        float2* g = (float2*)(out + (size_t)NB * CC * OUTN * OUTN);
        g[((size_t)n * OUTN + ho) * OUTN + wo] = make_float2(xg, yg);
    }
}

extern "C" void kernel_launch(void* const* d_in, const int* in_sizes, int n_in,
                              void* d_out, int out_size)
{
    const float* data = (const float*)d_in[0];
    const float* attx = (const float*)d_in[1];
    const float* atty = (const float*)d_in[2];
    float* out = (float*)d_out;

    const long long sampled_elems = (long long)NB * CC * OUTN * OUTN;            // 25,165,824
    const long long grid_elems    = (long long)NB * OUTN * OUTN * 2;             // 16,777,216
    const int writeGrid = ((long long)out_size >= sampled_elems + grid_elems) ? 1 : 0;

    waterfill_coords_kernel<<<NB, 512>>>(attx, atty);
    dim3 grid2(OUTN, NB);
    grid_sample_kernel<<<grid2, 512>>>(data, out, writeGrid);
}